// round 14
// baseline (speedup 1.0000x reference)
#include <cuda_runtime.h>
#include <cuda_fp16.h>
#include <math.h>
#include <stdint.h>

#define N_NODES 20000
#define N_EDGES 640000
#define DIM     128
#define KTOT    512     // A cols: [aggX | X | aggH | H]
#define NCOL    512     // 4 gates * 128 outputs, col = o*4 + g
#define MTILES  157     // ceil(20000/128)

// ===================== helpers =====================
__device__ __forceinline__ uint32_t smem_to_u32(const void* p) {
    uint32_t a;
    asm("{ .reg .u64 t; cvta.to.shared.u64 t, %1; cvt.u32.u64 %0, t; }" : "=r"(a) : "l"(p));
    return a;
}
#define CP_ASYNC16(sm, gp) \
    asm volatile("cp.async.cg.shared.global [%0], [%1], 16;" :: "r"(sm), "l"(gp) : "memory")
#define CP_COMMIT() asm volatile("cp.async.commit_group;" ::: "memory")
#define CP_WAIT(n)  asm volatile("cp.async.wait_group %0;" :: "n"(n) : "memory")

#define LDSM_X4(r0, r1, r2, r3, a) \
    asm volatile("ldmatrix.sync.aligned.m8n8.x4.shared.b16 {%0,%1,%2,%3}, [%4];" \
        : "=r"(r0), "=r"(r1), "=r"(r2), "=r"(r3) : "r"(a))

// fp16-accumulate MMA: d = a*b + d (d,c are the same 2 fp16x2 regs)
#define MMA_F16ACC(d01, a, b) \
    asm volatile("mma.sync.aligned.m16n8k16.row.col.f16.f16.f16.f16 " \
        "{%0,%1}, {%2,%3,%4,%5}, {%6,%7}, {%0,%1};" \
        : "+r"((d01)[0]), "+r"((d01)[1]) \
        : "r"((a)[0]), "r"((a)[1]), "r"((a)[2]), "r"((a)[3]), "r"((b)[0]), "r"((b)[1]))

// ===================== scratch =====================
__device__ int   g_cnt[N_NODES + 1];                    // slot N_NODES = done-counter
__device__ int   g_off[N_NODES + 1];
__device__ int   g_rank[N_EDGES];                       // edge rank within its dst bucket
__device__ uint2 g_edge[N_EDGES];                       // {src, weight bits}
__device__ __half g_Ah[(size_t)N_NODES * KTOT];         // fp16 A matrix [node][512]
__device__ __half g_Bh[(size_t)NCOL * KTOT];            // fp16 B^T [n][k], n = o*4+g

#define COUNT_BLOCKS 625                                 // 4 edges/thread
#define CONV_N2 (N_NODES * 64)                           // 2 cols per thread
#define PACK_N  (NCOL * KTOT)
#define PREP_BLOCKS ((CONV_N2 + PACK_N + 255) / 256)
#define CPS_BLOCKS  (COUNT_BLOCKS + PREP_BLOCKS)

// ===================== fused count(+rank) + prep + (last block) scan =====================
__global__ void count_prep_scan_kernel(const int* __restrict__ ei,
                                       const float* __restrict__ X, const float* __restrict__ H,
                                       const float* __restrict__ Wx_l, const float* __restrict__ Wx_r,
                                       const float* __restrict__ Wh_l, const float* __restrict__ Wh_r) {
    int b = blockIdx.x;
    if (b < COUNT_BLOCKS) {
        int e0 = b * 1024 + threadIdx.x;
#pragma unroll
        for (int j = 0; j < 4; j++) {
            int e = e0 + j * 256;
            if (e < N_EDGES) {
                int d = ei[N_EDGES + e];
                g_rank[e] = atomicAdd(&g_cnt[d], 1);
            }
        }
    } else {
        int idx = (b - COUNT_BLOCKS) * 256 + threadIdx.x;
        if (idx < CONV_N2) {
            int r = idx >> 6, c2 = idx & 63;          // 2 cols per thread
            float2 xv = *(const float2*)(X + (size_t)r * DIM + c2 * 2);
            float2 hv = *(const float2*)(H + (size_t)r * DIM + c2 * 2);
            size_t ba = (size_t)r * KTOT;
            *(__half2*)(g_Ah + ba + 128 + c2 * 2) = __floats2half2_rn(xv.x, xv.y);
            *(__half2*)(g_Ah + ba + 384 + c2 * 2) = __floats2half2_rn(hv.x, hv.y);
        } else {
            int j = idx - CONV_N2;
            if (j < PACK_N) {
                int n = j >> 9;
                int k = j & 511;
                int o = n >> 2, g = n & 3;
                int kb = k >> 7, d = k & 127;
                const float* W = (kb == 0) ? Wx_l : (kb == 1) ? Wx_r : (kb == 2) ? Wh_l : Wh_r;
                g_Bh[j] = __float2half_rn(W[(g * DIM + d) * DIM + o]);
            }
        }
    }

    // ---- last-block scan ----
    __threadfence();
    __shared__ int s_last;
    if (threadIdx.x == 0)
        s_last = (atomicAdd(&g_cnt[N_NODES], 1) == CPS_BLOCKS - 1) ? 1 : 0;
    __syncthreads();
    if (!s_last) return;

    const int PER = 79;
    int t = threadIdx.x;
    int base = t * PER;
    int sum = 0;
    for (int j = 0; j < PER; j++) {
        int i = base + j;
        if (i < N_NODES) sum += g_cnt[i];
    }
    int lane = t & 31, warp = t >> 5;
    int x = sum;
#pragma unroll
    for (int o = 1; o < 32; o <<= 1) {
        int y = __shfl_up_sync(0xFFFFFFFFu, x, o);
        if (lane >= o) x += y;
    }
    __shared__ int wsum[8];
    if (lane == 31) wsum[warp] = x;
    __syncthreads();
    if (warp == 0 && lane < 8) {
        int w = wsum[lane];
#pragma unroll
        for (int o = 1; o < 8; o <<= 1) {
            int y = __shfl_up_sync(0xFFu, w, o);
            if (lane >= o) w += y;
        }
        wsum[lane] = w;
    }
    __syncthreads();
    int warpbase = (warp > 0) ? wsum[warp - 1] : 0;
    int excl = warpbase + x - sum;
    for (int j = 0; j < PER; j++) {
        int i = base + j;
        if (i < N_NODES) {
            g_off[i] = excl;
            excl += g_cnt[i];
        }
    }
    if (t == 255) g_off[N_NODES] = warpbase + x;
}

// ===================== scatter: atomic-free via precomputed ranks, 4 edges/thread =====================
__global__ void scatter_kernel(const int* __restrict__ ei, const float* __restrict__ ew) {
    int e0 = blockIdx.x * 1024 + threadIdx.x;
    int dd[4], ss[4], rr[4];
    float ww[4];
#pragma unroll
    for (int j = 0; j < 4; j++) {
        int e = e0 + j * 256;
        if (e < N_EDGES) {
            dd[j] = ei[N_EDGES + e];
            ss[j] = ei[e];
            ww[j] = ew[e];
            rr[j] = g_rank[e];
        } else dd[j] = -1;
    }
#pragma unroll
    for (int j = 0; j < 4; j++)
        if (dd[j] >= 0) {
            int p = g_off[dd[j]] + rr[j];
            g_edge[p] = make_uint2((uint32_t)ss[j], __float_as_uint(ww[j]));
        }
}

// ===================== aggregation: 1 warp/node, 4-edge batch, fp32 FMA =====================
__global__ void aggregate_kernel() {
    int warp = (blockIdx.x * blockDim.x + threadIdx.x) >> 5;
    int lane = threadIdx.x & 31;
    if (warp >= N_NODES) return;
    int beg = g_off[warp], end = g_off[warp + 1];
    // lanes 0-15 -> X chunk (src cols 128-255), lanes 16-31 -> H chunk (src cols 384-511)
    uint32_t src_off = 128u + ((uint32_t)(lane >> 4) << 8) + ((uint32_t)(lane & 15) << 3);
    float acc[8] = {0.f, 0.f, 0.f, 0.f, 0.f, 0.f, 0.f, 0.f};
    int e = beg;
    for (; e + 4 <= end; e += 4) {
        uint2 ed0 = __ldg(&g_edge[e + 0]);
        uint2 ed1 = __ldg(&g_edge[e + 1]);
        uint2 ed2 = __ldg(&g_edge[e + 2]);
        uint2 ed3 = __ldg(&g_edge[e + 3]);
        uint4 v0 = __ldg((const uint4*)(g_Ah + (size_t)ed0.x * KTOT + src_off));
        uint4 v1 = __ldg((const uint4*)(g_Ah + (size_t)ed1.x * KTOT + src_off));
        uint4 v2 = __ldg((const uint4*)(g_Ah + (size_t)ed2.x * KTOT + src_off));
        uint4 v3 = __ldg((const uint4*)(g_Ah + (size_t)ed3.x * KTOT + src_off));
        float w0 = __uint_as_float(ed0.y), w1 = __uint_as_float(ed1.y);
        float w2 = __uint_as_float(ed2.y), w3 = __uint_as_float(ed3.y);
        float2 p;
        p = __half22float2(*(const __half2*)&v0.x); acc[0] = fmaf(w0, p.x, acc[0]); acc[1] = fmaf(w0, p.y, acc[1]);
        p = __half22float2(*(const __half2*)&v0.y); acc[2] = fmaf(w0, p.x, acc[2]); acc[3] = fmaf(w0, p.y, acc[3]);
        p = __half22float2(*(const __half2*)&v0.z); acc[4] = fmaf(w0, p.x, acc[4]); acc[5] = fmaf(w0, p.y, acc[5]);
        p = __half22float2(*(const __half2*)&v0.w); acc[6] = fmaf(w0, p.x, acc[6]); acc[7] = fmaf(w0, p.y, acc[7]);
        p = __half22float2(*(const __half2*)&v1.x); acc[0] = fmaf(w1, p.x, acc[0]); acc[1] = fmaf(w1, p.y, acc[1]);
        p = __half22float2(*(const __half2*)&v1.y); acc[2] = fmaf(w1, p.x, acc[2]); acc[3] = fmaf(w1, p.y, acc[3]);
        p = __half22float2(*(const __half2*)&v1.z); acc[4] = fmaf(w1, p.x, acc[4]); acc[5] = fmaf(w1, p.y, acc[5]);
        p = __half22float2(*(const __half2*)&v1.w); acc[6] = fmaf(w1, p.x, acc[6]); acc[7] = fmaf(w1, p.y, acc[7]);
        p = __half22float2(*(const __half2*)&v2.x); acc[0] = fmaf(w2, p.x, acc[0]); acc[1] = fmaf(w2, p.y, acc[1]);
        p = __half22float2(*(const __half2*)&v2.y); acc[2] = fmaf(w2, p.x, acc[2]); acc[3] = fmaf(w2, p.y, acc[3]);
        p = __half22float2(*(const __half2*)&v2.z); acc[4] = fmaf(w2, p.x, acc[4]); acc[5] = fmaf(w2, p.y, acc[5]);
        p = __half22float2(*(const __half2*)&v2.w); acc[6] = fmaf(w2, p.x, acc[6]); acc[7] = fmaf(w2, p.y, acc[7]);
        p = __half22float2(*(const __half2*)&v3.x); acc[0] = fmaf(w3, p.x, acc[0]); acc[1] = fmaf(w3, p.y, acc[1]);
        p = __half22float2(*(const __half2*)&v3.y); acc[2] = fmaf(w3, p.x, acc[2]); acc[3] = fmaf(w3, p.y, acc[3]);
        p = __half22float2(*(const __half2*)&v3.z); acc[4] = fmaf(w3, p.x, acc[4]); acc[5] = fmaf(w3, p.y, acc[5]);
        p = __half22float2(*(const __half2*)&v3.w); acc[6] = fmaf(w3, p.x, acc[6]); acc[7] = fmaf(w3, p.y, acc[7]);
    }
    for (; e < end; e++) {
        uint2 ed = __ldg(&g_edge[e]);
        float w = __uint_as_float(ed.y);
        uint4 v = __ldg((const uint4*)(g_Ah + (size_t)ed.x * KTOT + src_off));
        float2 p;
        p = __half22float2(*(const __half2*)&v.x); acc[0] = fmaf(w, p.x, acc[0]); acc[1] = fmaf(w, p.y, acc[1]);
        p = __half22float2(*(const __half2*)&v.y); acc[2] = fmaf(w, p.x, acc[2]); acc[3] = fmaf(w, p.y, acc[3]);
        p = __half22float2(*(const __half2*)&v.z); acc[4] = fmaf(w, p.x, acc[4]); acc[5] = fmaf(w, p.y, acc[5]);
        p = __half22float2(*(const __half2*)&v.w); acc[6] = fmaf(w, p.x, acc[6]); acc[7] = fmaf(w, p.y, acc[7]);
    }
    float inv = 1.0f / fmaxf((float)(end - beg), 1.0f);
    uint32_t dst_off = ((uint32_t)(lane >> 4) << 8) + ((uint32_t)(lane & 15) << 3);
    __half2 h0 = __floats2half2_rn(acc[0] * inv, acc[1] * inv);
    __half2 h1 = __floats2half2_rn(acc[2] * inv, acc[3] * inv);
    __half2 h2 = __floats2half2_rn(acc[4] * inv, acc[5] * inv);
    __half2 h3 = __floats2half2_rn(acc[6] * inv, acc[7] * inv);
    uint4 out;
    out.x = *(uint32_t*)&h0; out.y = *(uint32_t*)&h1;
    out.z = *(uint32_t*)&h2; out.w = *(uint32_t*)&h3;
    *(uint4*)(g_Ah + (size_t)warp * KTOT + dst_off) = out;
}

// ===================== fp16 warp-MMA GEMM (f16-acc k32 chunks) + fused LSTM =====================
// Block 128x128, 256 threads (8 warps 2x4), warp tile 64x32, 2 CTAs/SM.
// K: 16 tiles of 32 fp16, double-buffered. Per (mi,ni) per k-tile: 2 chained f16-acc
// MMAs then promote into fp32 accumulators. SMEM rows: 32 fp16 + 16B pad = 80B.
#define ROW_B    80
#define TILE_B   (128 * ROW_B)        // 10240
#define STAGE_B  (2 * TILE_B)         // 20480 (A then B)
#define DSTRIDE  132
#define GEMM_SMEM (128 * DSTRIDE * 4) // 67584 (covers 2*STAGE_B = 40960 pipeline)

__global__ void __launch_bounds__(256, 2) gemm_lstm_kernel(
    const float* __restrict__ C,
    const float* __restrict__ bx, const float* __restrict__ bh, const float* __restrict__ bg,
    const float* __restrict__ wc,
    float* __restrict__ outH, float* __restrict__ outC)
{
    extern __shared__ char sm[];
    uint32_t smb = smem_to_u32(sm);

    int tid = threadIdx.x;
    int wid = tid >> 5, lid = tid & 31;
    int ntile = blockIdx.x;        // 0..3 (128 n-cols each)
    int row0  = blockIdx.y * 128;

    // cp.async mapping: thread -> row = tid>>1, half = tid&1 (16 fp16 = 32B)
    int lrow = tid >> 1;
    int half = tid & 1;
    int arow = row0 + lrow; if (arow >= N_NODES) arow = N_NODES - 1;
    int brow = ntile * 128 + lrow;
    uint32_t dst_off = (uint32_t)lrow * ROW_B + half * 32;
    const __half* Ap = g_Ah + (size_t)arow * KTOT + half * 16;
    const __half* Bp = g_Bh + (size_t)brow * KTOT + half * 16;

    // warp tiling: 2x4, warp tile 64x32
    int mw = (wid >> 2) * 64;
    int nw = (wid & 3) * 32;
    int a_r = ((lid >> 3) & 1) * 8 + (lid & 7);
    int a_k = (lid >> 4) * 8;
    int b_r = (lid >> 4) * 8 + (lid & 7);
    int b_k = ((lid >> 3) & 1) * 8;

    uint32_t offA = (uint32_t)(mw + a_r) * ROW_B + a_k * 2;
    uint32_t offB = (uint32_t)TILE_B + (uint32_t)(nw + b_r) * ROW_B + b_k * 2;

    float acc[4][4][4];
#pragma unroll
    for (int i = 0; i < 4; i++)
#pragma unroll
        for (int j = 0; j < 4; j++)
#pragma unroll
            for (int q = 0; q < 4; q++) acc[i][j][q] = 0.f;

    // prologue: k-tile 0 -> stage 0
    {
        uint32_t da = smb + dst_off;
        uint32_t db = smb + TILE_B + dst_off;
        CP_ASYNC16(da,      Ap);
        CP_ASYNC16(da + 16, Ap + 8);
        CP_ASYNC16(db,      Bp);
        CP_ASYNC16(db + 16, Bp + 8);
        CP_COMMIT();
    }

    int buf = 0;
    for (int kt = 0; kt < 16; kt++) {
        CP_WAIT(0);
        __syncthreads();
        if (kt < 15) {
            int k1 = (kt + 1) * 32;
            uint32_t sbb = smb + (buf ^ 1) * STAGE_B;
            uint32_t da = sbb + dst_off;
            uint32_t db = sbb + TILE_B + dst_off;
            CP_ASYNC16(da,      Ap + k1);
            CP_ASYNC16(da + 16, Ap + k1 + 8);
            CP_ASYNC16(db,      Bp + k1);
            CP_ASYNC16(db + 16, Bp + k1 + 8);
            CP_COMMIT();
        }

        uint32_t sstage = smb + buf * STAGE_B;
        uint32_t aA = sstage + offA;
        uint32_t aB = sstage + offB;

        // load B fragments for both k-halves (16 regs)
        uint32_t Bf[2][4][2];
#pragma unroll
        for (int ks = 0; ks < 2; ks++)
#pragma unroll
            for (int nj = 0; nj < 2; nj++) {
                LDSM_X4(Bf[ks][2 * nj][0], Bf[ks][2 * nj][1],
                        Bf[ks][2 * nj + 1][0], Bf[ks][2 * nj + 1][1],
                        aB + nj * (16 * ROW_B) + ks * 32);
            }

#pragma unroll
        for (int mi = 0; mi < 4; mi++) {
            uint32_t Af0[4], Af1[4];
            LDSM_X4(Af0[0], Af0[1], Af0[2], Af0[3], aA + mi * (16 * ROW_B));
            LDSM_X4(Af1[0], Af1[1], Af1[2], Af1[3], aA + mi * (16 * ROW_B) + 32);
#pragma unroll
            for (int ni = 0; ni < 4; ni++) {
                uint32_t hd[2]; hd[0] = 0u; hd[1] = 0u;
                MMA_F16ACC(hd, Af0, Bf[0][ni]);   // k32 chunk accumulated in fp16
                MMA_F16ACC(hd, Af1, Bf[1][ni]);
                float2 p0 = __half22float2(*(__half2*)&hd[0]);
                float2 p1 = __half22float2(*(__half2*)&hd[1]);
                acc[mi][ni][0] += p0.x; acc[mi][ni][1] += p0.y;
                acc[mi][ni][2] += p1.x; acc[mi][ni][3] += p1.y;
            }
        }
        buf ^= 1;
    }
    __syncthreads();

    // epilogue: acc -> smem D[128][132]
    float* sD = (float*)sm;
    {
        int r0 = mw + (lid >> 2);
        int c0 = nw + (lid & 3) * 2;
#pragma unroll
        for (int mi = 0; mi < 4; mi++)
#pragma unroll
            for (int ni = 0; ni < 4; ni++) {
                int rr = r0 + mi * 16, cc = c0 + ni * 8;
                sD[rr * DSTRIDE + cc]           = acc[mi][ni][0];
                sD[rr * DSTRIDE + cc + 1]       = acc[mi][ni][1];
                sD[(rr + 8) * DSTRIDE + cc]     = acc[mi][ni][2];
                sD[(rr + 8) * DSTRIDE + cc + 1] = acc[mi][ni][3];
            }
    }
    __syncthreads();

    // fused LSTM: thread -> row = tid>>1, 16 outputs
    {
        int row = tid >> 1;
        int r = row0 + row;
        if (r < N_NODES) {
            int ob = (tid & 1) * 16;
            int o0 = ntile * 32 + ob;
#pragma unroll 4
            for (int j = 0; j < 16; j += 4) {
                float4 cold4 = *(const float4*)&C[(size_t)r * DIM + o0 + j];
                float co[4] = {cold4.x, cold4.y, cold4.z, cold4.w};
                float hnew[4], cnew[4];
#pragma unroll
                for (int q = 0; q < 4; q++) {
                    int o = o0 + j + q;
                    float4 gq = *(float4*)&sD[row * DSTRIDE + (ob + j + q) * 4];
                    float gI = gq.x + bx[0 * DIM + o] + bh[0 * DIM + o] + bg[0 * DIM + o] + wc[0 * DIM + o] * co[q];
                    float gF = gq.y + bx[1 * DIM + o] + bh[1 * DIM + o] + bg[1 * DIM + o] + wc[1 * DIM + o] * co[q];
                    float gT = gq.z + bx[2 * DIM + o] + bh[2 * DIM + o] + bg[2 * DIM + o];
                    float I = 1.f / (1.f + expf(-gI));
                    float F = 1.f / (1.f + expf(-gF));
                    float T = tanhf(gT);
                    float cn = fmaf(F, co[q], I * T);
                    float gO = gq.w + bx[3 * DIM + o] + bh[3 * DIM + o] + bg[3 * DIM + o] + wc[2 * DIM + o] * cn;
                    float O = 1.f / (1.f + expf(-gO));
                    hnew[q] = O * tanhf(cn);
                    cnew[q] = cn;
                }
                *(float4*)&outH[(size_t)r * DIM + o0 + j] = make_float4(hnew[0], hnew[1], hnew[2], hnew[3]);
                *(float4*)&outC[(size_t)r * DIM + o0 + j] = make_float4(cnew[0], cnew[1], cnew[2], cnew[3]);
            }
        }
    }
}

// ===================== launch =====================
extern "C" void kernel_launch(void* const* d_in, const int* in_sizes, int n_in,
                              void* d_out, int out_size) {
    const float* X    = (const float*)d_in[0];
    const int*   ei   = (const int*)  d_in[1];
    const float* ew   = (const float*)d_in[2];
    const float* H    = (const float*)d_in[3];
    const float* C    = (const float*)d_in[4];
    const float* Wx_l = (const float*)d_in[5];
    const float* Wx_r = (const float*)d_in[6];
    const float* bx   = (const float*)d_in[7];
    const float* Wh_l = (const float*)d_in[8];
    const float* Wh_r = (const float*)d_in[9];
    const float* bh   = (const float*)d_in[10];
    const float* wc   = (const float*)d_in[11];
    const float* bg   = (const float*)d_in[12];

    float* outH = (float*)d_out;
    float* outC = outH + (size_t)N_NODES * DIM;

    cudaFuncSetAttribute(gemm_lstm_kernel, cudaFuncAttributeMaxDynamicSharedMemorySize, GEMM_SMEM);

    void* cnt_ptr = nullptr;
    cudaGetSymbolAddress(&cnt_ptr, g_cnt);
    cudaMemsetAsync(cnt_ptr, 0, sizeof(int) * (N_NODES + 1));

    count_prep_scan_kernel<<<CPS_BLOCKS, 256>>>(ei, X, H, Wx_l, Wx_r, Wh_l, Wh_r);
    scatter_kernel<<<(N_EDGES + 1023) / 1024, 256>>>(ei, ew);
    aggregate_kernel<<<(N_NODES * 32 + 255) / 256, 256>>>();

    dim3 grid(4, MTILES);
    gemm_lstm_kernel<<<grid, 256, GEMM_SMEM>>>(C, bx, bh, bg, wc, outH, outC);
}

// round 15
// speedup vs baseline: 1.0184x; 1.0184x over previous
#include <cuda_runtime.h>
#include <cuda_fp16.h>
#include <math.h>
#include <stdint.h>

#define N_NODES 20000
#define N_EDGES 640000
#define DIM     128
#define KTOT    512     // A cols: [aggX | X | aggH | H]
#define NCOL    512     // 4 gates * 128 outputs, col = o*4 + g
#define MTILES  157     // ceil(20000/128)

// ===================== helpers =====================
__device__ __forceinline__ uint32_t smem_to_u32(const void* p) {
    uint32_t a;
    asm("{ .reg .u64 t; cvta.to.shared.u64 t, %1; cvt.u32.u64 %0, t; }" : "=r"(a) : "l"(p));
    return a;
}
#define CP_ASYNC16(sm, gp) \
    asm volatile("cp.async.cg.shared.global [%0], [%1], 16;" :: "r"(sm), "l"(gp) : "memory")
#define CP_COMMIT() asm volatile("cp.async.commit_group;" ::: "memory")
#define CP_WAIT(n)  asm volatile("cp.async.wait_group %0;" :: "n"(n) : "memory")

#define LDSM_X4(r0, r1, r2, r3, a) \
    asm volatile("ldmatrix.sync.aligned.m8n8.x4.shared.b16 {%0,%1,%2,%3}, [%4];" \
        : "=r"(r0), "=r"(r1), "=r"(r2), "=r"(r3) : "r"(a))

#define MMA_F16(d, a, b) \
    asm volatile("mma.sync.aligned.m16n8k16.row.col.f32.f16.f16.f32 " \
        "{%0,%1,%2,%3}, {%4,%5,%6,%7}, {%8,%9}, {%0,%1,%2,%3};" \
        : "+f"((d)[0]), "+f"((d)[1]), "+f"((d)[2]), "+f"((d)[3]) \
        : "r"((a)[0]), "r"((a)[1]), "r"((a)[2]), "r"((a)[3]), "r"((b)[0]), "r"((b)[1]))

// ===================== scratch =====================
__device__ int   g_cnt[N_NODES + 1];                    // slot N_NODES = done-counter (self-restoring)
__device__ int   g_off[N_NODES + 1];
__device__ int   g_rank[N_EDGES];                       // edge rank within its dst bucket
__device__ uint2 g_edge[N_EDGES];                       // {src, weight bits}
__device__ __half g_Ah[(size_t)N_NODES * KTOT];         // fp16 A matrix [node][512]
__device__ __half g_Bh[(size_t)NCOL * KTOT];            // fp16 B^T [n][k], n = o*4+g

#define COUNT_BLOCKS 625                                 // 4 edges/thread
#define CONV_N2 (N_NODES * 64)                           // 2 cols per thread
#define PACK_N  (NCOL * KTOT)
#define PREP_BLOCKS ((CONV_N2 + PACK_N + 255) / 256)

// ===================== prep (side stream): fp16 X/H into g_A + B pack =====================
__global__ void prep_kernel(const float* __restrict__ X, const float* __restrict__ H,
                            const float* __restrict__ Wx_l, const float* __restrict__ Wx_r,
                            const float* __restrict__ Wh_l, const float* __restrict__ Wh_r) {
    int idx = blockIdx.x * 256 + threadIdx.x;
    if (idx < CONV_N2) {
        int r = idx >> 6, c2 = idx & 63;          // 2 cols per thread
        float2 xv = *(const float2*)(X + (size_t)r * DIM + c2 * 2);
        float2 hv = *(const float2*)(H + (size_t)r * DIM + c2 * 2);
        size_t ba = (size_t)r * KTOT;
        *(__half2*)(g_Ah + ba + 128 + c2 * 2) = __floats2half2_rn(xv.x, xv.y);
        *(__half2*)(g_Ah + ba + 384 + c2 * 2) = __floats2half2_rn(hv.x, hv.y);
    } else {
        int j = idx - CONV_N2;
        if (j < PACK_N) {
            int n = j >> 9;
            int k = j & 511;
            int o = n >> 2, g = n & 3;
            int kb = k >> 7, d = k & 127;
            const float* W = (kb == 0) ? Wx_l : (kb == 1) ? Wx_r : (kb == 2) ? Wh_l : Wh_r;
            g_Bh[j] = __float2half_rn(W[(g * DIM + d) * DIM + o]);
        }
    }
}

// ===================== count(+rank) + last-block scan (self-restoring) =====================
__global__ void count_scan_kernel(const int* __restrict__ ei) {
    int b = blockIdx.x;
    int e0 = b * 1024 + threadIdx.x;
#pragma unroll
    for (int j = 0; j < 4; j++) {
        int e = e0 + j * 256;
        if (e < N_EDGES) {
            int d = ei[N_EDGES + e];
            g_rank[e] = atomicAdd(&g_cnt[d], 1);
        }
    }

    // ---- last-block scan ----
    __threadfence();
    __shared__ int s_last;
    if (threadIdx.x == 0)
        s_last = (atomicAdd(&g_cnt[N_NODES], 1) == COUNT_BLOCKS - 1) ? 1 : 0;
    __syncthreads();
    if (!s_last) return;

    const int PER = 79;
    int t = threadIdx.x;
    int base = t * PER;
    int sum = 0;
    for (int j = 0; j < PER; j++) {
        int i = base + j;
        if (i < N_NODES) sum += g_cnt[i];
    }
    int lane = t & 31, warp = t >> 5;
    int x = sum;
#pragma unroll
    for (int o = 1; o < 32; o <<= 1) {
        int y = __shfl_up_sync(0xFFFFFFFFu, x, o);
        if (lane >= o) x += y;
    }
    __shared__ int wsum[8];
    if (lane == 31) wsum[warp] = x;
    __syncthreads();
    if (warp == 0 && lane < 8) {
        int w = wsum[lane];
#pragma unroll
        for (int o = 1; o < 8; o <<= 1) {
            int y = __shfl_up_sync(0xFFu, w, o);
            if (lane >= o) w += y;
        }
        wsum[lane] = w;
    }
    __syncthreads();
    int warpbase = (warp > 0) ? wsum[warp - 1] : 0;
    int excl = warpbase + x - sum;
    for (int j = 0; j < PER; j++) {
        int i = base + j;
        if (i < N_NODES) {
            int c = g_cnt[i];
            g_off[i] = excl;
            excl += c;
            g_cnt[i] = 0;              // self-restore for next replay
        }
    }
    if (t == 255) {
        g_off[N_NODES] = warpbase + x;
        g_cnt[N_NODES] = 0;            // reset done-counter for next replay
    }
}

// ===================== scatter: atomic-free via precomputed ranks, 4 edges/thread =====================
__global__ void scatter_kernel(const int* __restrict__ ei, const float* __restrict__ ew) {
    int e0 = blockIdx.x * 1024 + threadIdx.x;
    int dd[4], ss[4], rr[4];
    float ww[4];
#pragma unroll
    for (int j = 0; j < 4; j++) {
        int e = e0 + j * 256;
        if (e < N_EDGES) {
            dd[j] = ei[N_EDGES + e];
            ss[j] = ei[e];
            ww[j] = ew[e];
            rr[j] = g_rank[e];
        } else dd[j] = -1;
    }
#pragma unroll
    for (int j = 0; j < 4; j++)
        if (dd[j] >= 0) {
            int p = g_off[dd[j]] + rr[j];
            g_edge[p] = make_uint2((uint32_t)ss[j], __float_as_uint(ww[j]));
        }
}

// ===================== aggregation: 1 warp/node, 4-edge batch, fp32 FMA =====================
__global__ void aggregate_kernel() {
    int warp = (blockIdx.x * blockDim.x + threadIdx.x) >> 5;
    int lane = threadIdx.x & 31;
    if (warp >= N_NODES) return;
    int beg = g_off[warp], end = g_off[warp + 1];
    // lanes 0-15 -> X chunk (src cols 128-255), lanes 16-31 -> H chunk (src cols 384-511)
    uint32_t src_off = 128u + ((uint32_t)(lane >> 4) << 8) + ((uint32_t)(lane & 15) << 3);
    float acc[8] = {0.f, 0.f, 0.f, 0.f, 0.f, 0.f, 0.f, 0.f};
    int e = beg;
    for (; e + 4 <= end; e += 4) {
        uint2 ed0 = __ldg(&g_edge[e + 0]);
        uint2 ed1 = __ldg(&g_edge[e + 1]);
        uint2 ed2 = __ldg(&g_edge[e + 2]);
        uint2 ed3 = __ldg(&g_edge[e + 3]);
        uint4 v0 = __ldg((const uint4*)(g_Ah + (size_t)ed0.x * KTOT + src_off));
        uint4 v1 = __ldg((const uint4*)(g_Ah + (size_t)ed1.x * KTOT + src_off));
        uint4 v2 = __ldg((const uint4*)(g_Ah + (size_t)ed2.x * KTOT + src_off));
        uint4 v3 = __ldg((const uint4*)(g_Ah + (size_t)ed3.x * KTOT + src_off));
        float w0 = __uint_as_float(ed0.y), w1 = __uint_as_float(ed1.y);
        float w2 = __uint_as_float(ed2.y), w3 = __uint_as_float(ed3.y);
        float2 p;
        p = __half22float2(*(const __half2*)&v0.x); acc[0] = fmaf(w0, p.x, acc[0]); acc[1] = fmaf(w0, p.y, acc[1]);
        p = __half22float2(*(const __half2*)&v0.y); acc[2] = fmaf(w0, p.x, acc[2]); acc[3] = fmaf(w0, p.y, acc[3]);
        p = __half22float2(*(const __half2*)&v0.z); acc[4] = fmaf(w0, p.x, acc[4]); acc[5] = fmaf(w0, p.y, acc[5]);
        p = __half22float2(*(const __half2*)&v0.w); acc[6] = fmaf(w0, p.x, acc[6]); acc[7] = fmaf(w0, p.y, acc[7]);
        p = __half22float2(*(const __half2*)&v1.x); acc[0] = fmaf(w1, p.x, acc[0]); acc[1] = fmaf(w1, p.y, acc[1]);
        p = __half22float2(*(const __half2*)&v1.y); acc[2] = fmaf(w1, p.x, acc[2]); acc[3] = fmaf(w1, p.y, acc[3]);
        p = __half22float2(*(const __half2*)&v1.z); acc[4] = fmaf(w1, p.x, acc[4]); acc[5] = fmaf(w1, p.y, acc[5]);
        p = __half22float2(*(const __half2*)&v1.w); acc[6] = fmaf(w1, p.x, acc[6]); acc[7] = fmaf(w1, p.y, acc[7]);
        p = __half22float2(*(const __half2*)&v2.x); acc[0] = fmaf(w2, p.x, acc[0]); acc[1] = fmaf(w2, p.y, acc[1]);
        p = __half22float2(*(const __half2*)&v2.y); acc[2] = fmaf(w2, p.x, acc[2]); acc[3] = fmaf(w2, p.y, acc[3]);
        p = __half22float2(*(const __half2*)&v2.z); acc[4] = fmaf(w2, p.x, acc[4]); acc[5] = fmaf(w2, p.y, acc[5]);
        p = __half22float2(*(const __half2*)&v2.w); acc[6] = fmaf(w2, p.x, acc[6]); acc[7] = fmaf(w2, p.y, acc[7]);
        p = __half22float2(*(const __half2*)&v3.x); acc[0] = fmaf(w3, p.x, acc[0]); acc[1] = fmaf(w3, p.y, acc[1]);
        p = __half22float2(*(const __half2*)&v3.y); acc[2] = fmaf(w3, p.x, acc[2]); acc[3] = fmaf(w3, p.y, acc[3]);
        p = __half22float2(*(const __half2*)&v3.z); acc[4] = fmaf(w3, p.x, acc[4]); acc[5] = fmaf(w3, p.y, acc[5]);
        p = __half22float2(*(const __half2*)&v3.w); acc[6] = fmaf(w3, p.x, acc[6]); acc[7] = fmaf(w3, p.y, acc[7]);
    }
    for (; e < end; e++) {
        uint2 ed = __ldg(&g_edge[e]);
        float w = __uint_as_float(ed.y);
        uint4 v = __ldg((const uint4*)(g_Ah + (size_t)ed.x * KTOT + src_off));
        float2 p;
        p = __half22float2(*(const __half2*)&v.x); acc[0] = fmaf(w, p.x, acc[0]); acc[1] = fmaf(w, p.y, acc[1]);
        p = __half22float2(*(const __half2*)&v.y); acc[2] = fmaf(w, p.x, acc[2]); acc[3] = fmaf(w, p.y, acc[3]);
        p = __half22float2(*(const __half2*)&v.z); acc[4] = fmaf(w, p.x, acc[4]); acc[5] = fmaf(w, p.y, acc[5]);
        p = __half22float2(*(const __half2*)&v.w); acc[6] = fmaf(w, p.x, acc[6]); acc[7] = fmaf(w, p.y, acc[7]);
    }
    float inv = 1.0f / fmaxf((float)(end - beg), 1.0f);
    // dst: aggX -> cols 0-127 (lanes 0-15), aggH -> cols 256-383 (lanes 16-31)
    uint32_t dst_off = ((uint32_t)(lane >> 4) << 8) + ((uint32_t)(lane & 15) << 3);
    __half2 h0 = __floats2half2_rn(acc[0] * inv, acc[1] * inv);
    __half2 h1 = __floats2half2_rn(acc[2] * inv, acc[3] * inv);
    __half2 h2 = __floats2half2_rn(acc[4] * inv, acc[5] * inv);
    __half2 h3 = __floats2half2_rn(acc[6] * inv, acc[7] * inv);
    uint4 out;
    out.x = *(uint32_t*)&h0; out.y = *(uint32_t*)&h1;
    out.z = *(uint32_t*)&h2; out.w = *(uint32_t*)&h3;
    *(uint4*)(g_Ah + (size_t)warp * KTOT + dst_off) = out;
}

// ===================== fp16 warp-MMA GEMM + fused LSTM (R13-proven) =====================
// Block 128x128, 256 threads (8 warps 2x4), warp tile 64x32, 2 CTAs/SM.
// K: 16 tiles of 32 fp16, double-buffered. SMEM rows: 32 fp16 (64B) + 16B pad = 80B.
#define ROW_B    80
#define TILE_B   (128 * ROW_B)        // 10240
#define STAGE_B  (2 * TILE_B)         // 20480 (A then B)
#define DSTRIDE  132
#define GEMM_SMEM (128 * DSTRIDE * 4) // 67584 (covers 2*STAGE_B = 40960 pipeline)

__global__ void __launch_bounds__(256, 2) gemm_lstm_kernel(
    const float* __restrict__ C,
    const float* __restrict__ bx, const float* __restrict__ bh, const float* __restrict__ bg,
    const float* __restrict__ wc,
    float* __restrict__ outH, float* __restrict__ outC)
{
    extern __shared__ char sm[];
    uint32_t smb = smem_to_u32(sm);

    int tid = threadIdx.x;
    int wid = tid >> 5, lid = tid & 31;
    int ntile = blockIdx.x;        // 0..3 (128 n-cols each)
    int row0  = blockIdx.y * 128;

    // cp.async mapping: thread -> row = tid>>1, half = tid&1 (16 fp16 = 32B)
    int lrow = tid >> 1;
    int half = tid & 1;
    int arow = row0 + lrow; if (arow >= N_NODES) arow = N_NODES - 1;
    int brow = ntile * 128 + lrow;
    uint32_t dst_off = (uint32_t)lrow * ROW_B + half * 32;
    const __half* Ap = g_Ah + (size_t)arow * KTOT + half * 16;
    const __half* Bp = g_Bh + (size_t)brow * KTOT + half * 16;

    // warp tiling: 2x4, warp tile 64x32
    int mw = (wid >> 2) * 64;
    int nw = (wid & 3) * 32;
    int a_r = ((lid >> 3) & 1) * 8 + (lid & 7);
    int a_k = (lid >> 4) * 8;
    int b_r = (lid >> 4) * 8 + (lid & 7);
    int b_k = ((lid >> 3) & 1) * 8;

    uint32_t offA = (uint32_t)(mw + a_r) * ROW_B + a_k * 2;
    uint32_t offB = (uint32_t)TILE_B + (uint32_t)(nw + b_r) * ROW_B + b_k * 2;

    float acc[4][4][4];
#pragma unroll
    for (int i = 0; i < 4; i++)
#pragma unroll
        for (int j = 0; j < 4; j++)
#pragma unroll
            for (int q = 0; q < 4; q++) acc[i][j][q] = 0.f;

    // prologue: k-tile 0 -> stage 0
    {
        uint32_t da = smb + dst_off;
        uint32_t db = smb + TILE_B + dst_off;
        CP_ASYNC16(da,      Ap);
        CP_ASYNC16(da + 16, Ap + 8);
        CP_ASYNC16(db,      Bp);
        CP_ASYNC16(db + 16, Bp + 8);
        CP_COMMIT();
    }

    int buf = 0;
    for (int kt = 0; kt < 16; kt++) {
        CP_WAIT(0);
        __syncthreads();
        if (kt < 15) {
            int k1 = (kt + 1) * 32;
            uint32_t sbb = smb + (buf ^ 1) * STAGE_B;
            uint32_t da = sbb + dst_off;
            uint32_t db = sbb + TILE_B + dst_off;
            CP_ASYNC16(da,      Ap + k1);
            CP_ASYNC16(da + 16, Ap + k1 + 8);
            CP_ASYNC16(db,      Bp + k1);
            CP_ASYNC16(db + 16, Bp + k1 + 8);
            CP_COMMIT();
        }

        uint32_t sstage = smb + buf * STAGE_B;
        uint32_t aA = sstage + offA;
        uint32_t aB = sstage + offB;

#pragma unroll
        for (int ks = 0; ks < 2; ks++) {
            uint32_t koff = ks * 32;   // 16 fp16 = 32B
            uint32_t Bf[4][2];
#pragma unroll
            for (int nj = 0; nj < 2; nj++) {
                LDSM_X4(Bf[2 * nj][0], Bf[2 * nj][1], Bf[2 * nj + 1][0], Bf[2 * nj + 1][1],
                        aB + nj * (16 * ROW_B) + koff);
            }
#pragma unroll
            for (int mi = 0; mi < 4; mi++) {
                uint32_t Af[4];
                LDSM_X4(Af[0], Af[1], Af[2], Af[3], aA + mi * (16 * ROW_B) + koff);
#pragma unroll
                for (int ni = 0; ni < 4; ni++)
                    MMA_F16(acc[mi][ni], Af, Bf[ni]);
            }
        }
        buf ^= 1;
    }
    __syncthreads();

    // epilogue: acc -> smem D[128][132]
    float* sD = (float*)sm;
    {
        int r0 = mw + (lid >> 2);
        int c0 = nw + (lid & 3) * 2;
#pragma unroll
        for (int mi = 0; mi < 4; mi++)
#pragma unroll
            for (int ni = 0; ni < 4; ni++) {
                int rr = r0 + mi * 16, cc = c0 + ni * 8;
                sD[rr * DSTRIDE + cc]           = acc[mi][ni][0];
                sD[rr * DSTRIDE + cc + 1]       = acc[mi][ni][1];
                sD[(rr + 8) * DSTRIDE + cc]     = acc[mi][ni][2];
                sD[(rr + 8) * DSTRIDE + cc + 1] = acc[mi][ni][3];
            }
    }
    __syncthreads();

    // fused LSTM: thread -> row = tid>>1, 16 outputs
    {
        int row = tid >> 1;
        int r = row0 + row;
        if (r < N_NODES) {
            int ob = (tid & 1) * 16;
            int o0 = ntile * 32 + ob;
#pragma unroll 4
            for (int j = 0; j < 16; j += 4) {
                float4 cold4 = *(const float4*)&C[(size_t)r * DIM + o0 + j];
                float co[4] = {cold4.x, cold4.y, cold4.z, cold4.w};
                float hnew[4], cnew[4];
#pragma unroll
                for (int q = 0; q < 4; q++) {
                    int o = o0 + j + q;
                    float4 gq = *(float4*)&sD[row * DSTRIDE + (ob + j + q) * 4];
                    float gI = gq.x + bx[0 * DIM + o] + bh[0 * DIM + o] + bg[0 * DIM + o] + wc[0 * DIM + o] * co[q];
                    float gF = gq.y + bx[1 * DIM + o] + bh[1 * DIM + o] + bg[1 * DIM + o] + wc[1 * DIM + o] * co[q];
                    float gT = gq.z + bx[2 * DIM + o] + bh[2 * DIM + o] + bg[2 * DIM + o];
                    float I = 1.f / (1.f + expf(-gI));
                    float F = 1.f / (1.f + expf(-gF));
                    float T = tanhf(gT);
                    float cn = fmaf(F, co[q], I * T);
                    float gO = gq.w + bx[3 * DIM + o] + bh[3 * DIM + o] + bg[3 * DIM + o] + wc[2 * DIM + o] * cn;
                    float O = 1.f / (1.f + expf(-gO));
                    hnew[q] = O * tanhf(cn);
                    cnew[q] = cn;
                }
                *(float4*)&outH[(size_t)r * DIM + o0 + j] = make_float4(hnew[0], hnew[1], hnew[2], hnew[3]);
                *(float4*)&outC[(size_t)r * DIM + o0 + j] = make_float4(cnew[0], cnew[1], cnew[2], cnew[3]);
            }
        }
    }
}

// ===================== launch =====================
extern "C" void kernel_launch(void* const* d_in, const int* in_sizes, int n_in,
                              void* d_out, int out_size) {
    const float* X    = (const float*)d_in[0];
    const int*   ei   = (const int*)  d_in[1];
    const float* ew   = (const float*)d_in[2];
    const float* H    = (const float*)d_in[3];
    const float* C    = (const float*)d_in[4];
    const float* Wx_l = (const float*)d_in[5];
    const float* Wx_r = (const float*)d_in[6];
    const float* bx   = (const float*)d_in[7];
    const float* Wh_l = (const float*)d_in[8];
    const float* Wh_r = (const float*)d_in[9];
    const float* bh   = (const float*)d_in[10];
    const float* wc   = (const float*)d_in[11];
    const float* bg   = (const float*)d_in[12];

    float* outH = (float*)d_out;
    float* outC = outH + (size_t)N_NODES * DIM;

    cudaFuncSetAttribute(gemm_lstm_kernel, cudaFuncAttributeMaxDynamicSharedMemorySize, GEMM_SMEM);

    // side stream + fork/join events (created per call; only correctness+capture calls exist)
    cudaStream_t s2;
    cudaStreamCreateWithFlags(&s2, cudaStreamNonBlocking);
    cudaEvent_t evFork, evPrep;
    cudaEventCreateWithFlags(&evFork, cudaEventDisableTiming);
    cudaEventCreateWithFlags(&evPrep, cudaEventDisableTiming);

    // fork: prep (X/H convert + B pack) on side stream, overlapping CSR build
    cudaEventRecord(evFork, 0);
    cudaStreamWaitEvent(s2, evFork, 0);
    prep_kernel<<<PREP_BLOCKS, 256, 0, s2>>>(X, H, Wx_l, Wx_r, Wh_l, Wh_r);

    // main stream: count(+rank) + scan (self-restoring), then scatter
    count_scan_kernel<<<COUNT_BLOCKS, 256>>>(ei);
    scatter_kernel<<<(N_EDGES + 1023) / 1024, 256>>>(ei, ew);

    // join: aggregate needs prep's X/H fp16 data
    cudaEventRecord(evPrep, s2);
    cudaStreamWaitEvent(0, evPrep, 0);
    aggregate_kernel<<<(N_NODES * 32 + 255) / 256, 256>>>();

    dim3 grid(4, MTILES);
    gemm_lstm_kernel<<<grid, 256, GEMM_SMEM>>>(C, bx, bh, bg, wc, outH, outC);
}

// round 16
// speedup vs baseline: 1.0501x; 1.0311x over previous
#include <cuda_runtime.h>
#include <cuda_fp16.h>
#include <math.h>
#include <stdint.h>

#define N_NODES 20000
#define N_EDGES 640000
#define DIM     128
#define KTOT    512     // A cols: [aggX | X | aggH | H]
#define NCOL    512     // 4 gates * 128 outputs, col = o*4 + g
#define MTILES  157     // ceil(20000/128)

// ===================== helpers =====================
__device__ __forceinline__ uint32_t smem_to_u32(const void* p) {
    uint32_t a;
    asm("{ .reg .u64 t; cvta.to.shared.u64 t, %1; cvt.u32.u64 %0, t; }" : "=r"(a) : "l"(p));
    return a;
}
#define CP_ASYNC16(sm, gp) \
    asm volatile("cp.async.cg.shared.global [%0], [%1], 16;" :: "r"(sm), "l"(gp) : "memory")
#define CP_COMMIT() asm volatile("cp.async.commit_group;" ::: "memory")
#define CP_WAIT(n)  asm volatile("cp.async.wait_group %0;" :: "n"(n) : "memory")

#define LDSM_X4(r0, r1, r2, r3, a) \
    asm volatile("ldmatrix.sync.aligned.m8n8.x4.shared.b16 {%0,%1,%2,%3}, [%4];" \
        : "=r"(r0), "=r"(r1), "=r"(r2), "=r"(r3) : "r"(a))

#define MMA_F16(d, a, b) \
    asm volatile("mma.sync.aligned.m16n8k16.row.col.f32.f16.f16.f32 " \
        "{%0,%1,%2,%3}, {%4,%5,%6,%7}, {%8,%9}, {%0,%1,%2,%3};" \
        : "+f"((d)[0]), "+f"((d)[1]), "+f"((d)[2]), "+f"((d)[3]) \
        : "r"((a)[0]), "r"((a)[1]), "r"((a)[2]), "r"((a)[3]), "r"((b)[0]), "r"((b)[1]))

// ===================== scratch =====================
__device__ int   g_cnt[N_NODES + 1];                    // slot N_NODES = done-counter (self-restoring)
__device__ int   g_off[N_NODES + 1];
__device__ int   g_rank[N_EDGES];                       // edge rank within its dst bucket
__device__ uint2 g_edge[N_EDGES];                       // {src, weight bits}
__device__ __half g_Ah[(size_t)N_NODES * KTOT];         // fp16 A matrix [node][512]
__device__ __half g_Bh[(size_t)NCOL * KTOT];            // fp16 B^T [n][k], n = o*4+g

#define COUNT_BLOCKS 625                                 // 4 edges/thread
#define CONV_N4 (N_NODES * 32)                           // 4 cols per thread
#define PACK_N  (NCOL * KTOT)
#define PREP_BLOCKS ((CONV_N4 + PACK_N + 255) / 256)
#define CPS_BLOCKS  (COUNT_BLOCKS + PREP_BLOCKS)

// ===================== fused count(+rank) + prep + (last block) scan, self-restoring =====================
__global__ void count_prep_scan_kernel(const int* __restrict__ ei,
                                       const float* __restrict__ X, const float* __restrict__ H,
                                       const float* __restrict__ Wx_l, const float* __restrict__ Wx_r,
                                       const float* __restrict__ Wh_l, const float* __restrict__ Wh_r) {
    int b = blockIdx.x;
    if (b < COUNT_BLOCKS) {
        int e0 = b * 1024 + threadIdx.x;
#pragma unroll
        for (int j = 0; j < 4; j++) {
            int e = e0 + j * 256;
            if (e < N_EDGES) {
                int d = ei[N_EDGES + e];
                g_rank[e] = atomicAdd(&g_cnt[d], 1);
            }
        }
    } else {
        int idx = (b - COUNT_BLOCKS) * 256 + threadIdx.x;
        if (idx < CONV_N4) {
            int r = idx >> 5, c4 = idx & 31;          // 4 cols per thread
            float4 xv = *(const float4*)(X + (size_t)r * DIM + c4 * 4);
            float4 hv = *(const float4*)(H + (size_t)r * DIM + c4 * 4);
            size_t ba = (size_t)r * KTOT;
            __half2* px = (__half2*)(g_Ah + ba + 128 + c4 * 4);
            px[0] = __floats2half2_rn(xv.x, xv.y);
            px[1] = __floats2half2_rn(xv.z, xv.w);
            __half2* ph = (__half2*)(g_Ah + ba + 384 + c4 * 4);
            ph[0] = __floats2half2_rn(hv.x, hv.y);
            ph[1] = __floats2half2_rn(hv.z, hv.w);
        } else {
            int j = idx - CONV_N4;
            if (j < PACK_N) {
                int n = j >> 9;
                int k = j & 511;
                int o = n >> 2, g = n & 3;
                int kb = k >> 7, d = k & 127;
                const float* W = (kb == 0) ? Wx_l : (kb == 1) ? Wx_r : (kb == 2) ? Wh_l : Wh_r;
                g_Bh[j] = __float2half_rn(W[(g * DIM + d) * DIM + o]);
            }
        }
    }

    // ---- last-block scan (re-zeroes counts for next graph replay) ----
    __threadfence();
    __shared__ int s_last;
    if (threadIdx.x == 0)
        s_last = (atomicAdd(&g_cnt[N_NODES], 1) == CPS_BLOCKS - 1) ? 1 : 0;
    __syncthreads();
    if (!s_last) return;

    const int PER = 79;
    int t = threadIdx.x;
    int base = t * PER;
    int sum = 0;
    for (int j = 0; j < PER; j++) {
        int i = base + j;
        if (i < N_NODES) sum += g_cnt[i];
    }
    int lane = t & 31, warp = t >> 5;
    int x = sum;
#pragma unroll
    for (int o = 1; o < 32; o <<= 1) {
        int y = __shfl_up_sync(0xFFFFFFFFu, x, o);
        if (lane >= o) x += y;
    }
    __shared__ int wsum[8];
    if (lane == 31) wsum[warp] = x;
    __syncthreads();
    if (warp == 0 && lane < 8) {
        int w = wsum[lane];
#pragma unroll
        for (int o = 1; o < 8; o <<= 1) {
            int y = __shfl_up_sync(0xFFu, w, o);
            if (lane >= o) w += y;
        }
        wsum[lane] = w;
    }
    __syncthreads();
    int warpbase = (warp > 0) ? wsum[warp - 1] : 0;
    int excl = warpbase + x - sum;
    for (int j = 0; j < PER; j++) {
        int i = base + j;
        if (i < N_NODES) {
            int c = g_cnt[i];
            g_off[i] = excl;
            excl += c;
            g_cnt[i] = 0;              // self-restore for next replay
        }
    }
    if (t == 255) {
        g_off[N_NODES] = warpbase + x;
        g_cnt[N_NODES] = 0;            // reset done-counter
    }
}

// ===================== scatter: atomic-free via precomputed ranks, 4 edges/thread =====================
__global__ void scatter_kernel(const int* __restrict__ ei, const float* __restrict__ ew) {
    int e0 = blockIdx.x * 1024 + threadIdx.x;
    int dd[4], ss[4], rr[4];
    float ww[4];
#pragma unroll
    for (int j = 0; j < 4; j++) {
        int e = e0 + j * 256;
        if (e < N_EDGES) {
            dd[j] = ei[N_EDGES + e];
            ss[j] = ei[e];
            ww[j] = ew[e];
            rr[j] = g_rank[e];
        } else dd[j] = -1;
    }
#pragma unroll
    for (int j = 0; j < 4; j++)
        if (dd[j] >= 0) {
            int p = g_off[dd[j]] + rr[j];
            g_edge[p] = make_uint2((uint32_t)ss[j], __float_as_uint(ww[j]));
        }
}

// ===================== aggregation: 1 warp/node, 8-edge batch, fp32 FMA =====================
__global__ void aggregate_kernel() {
    int warp = (blockIdx.x * blockDim.x + threadIdx.x) >> 5;
    int lane = threadIdx.x & 31;
    if (warp >= N_NODES) return;
    int beg = g_off[warp], end = g_off[warp + 1];
    // lanes 0-15 -> X chunk (src cols 128-255), lanes 16-31 -> H chunk (src cols 384-511)
    uint32_t src_off = 128u + ((uint32_t)(lane >> 4) << 8) + ((uint32_t)(lane & 15) << 3);
    float acc[8] = {0.f, 0.f, 0.f, 0.f, 0.f, 0.f, 0.f, 0.f};
    int e = beg;
    for (; e + 8 <= end; e += 8) {
        uint2 ed[8];
#pragma unroll
        for (int j = 0; j < 8; j++) ed[j] = __ldg(&g_edge[e + j]);
        uint4 v[8];
#pragma unroll
        for (int j = 0; j < 8; j++) v[j] = __ldg((const uint4*)(g_Ah + (size_t)ed[j].x * KTOT + src_off));
#pragma unroll
        for (int j = 0; j < 8; j++) {
            float w = __uint_as_float(ed[j].y);
            float2 p;
            p = __half22float2(*(const __half2*)&v[j].x); acc[0] = fmaf(w, p.x, acc[0]); acc[1] = fmaf(w, p.y, acc[1]);
            p = __half22float2(*(const __half2*)&v[j].y); acc[2] = fmaf(w, p.x, acc[2]); acc[3] = fmaf(w, p.y, acc[3]);
            p = __half22float2(*(const __half2*)&v[j].z); acc[4] = fmaf(w, p.x, acc[4]); acc[5] = fmaf(w, p.y, acc[5]);
            p = __half22float2(*(const __half2*)&v[j].w); acc[6] = fmaf(w, p.x, acc[6]); acc[7] = fmaf(w, p.y, acc[7]);
        }
    }
    for (; e < end; e++) {
        uint2 ed = __ldg(&g_edge[e]);
        float w = __uint_as_float(ed.y);
        uint4 vv = __ldg((const uint4*)(g_Ah + (size_t)ed.x * KTOT + src_off));
        float2 p;
        p = __half22float2(*(const __half2*)&vv.x); acc[0] = fmaf(w, p.x, acc[0]); acc[1] = fmaf(w, p.y, acc[1]);
        p = __half22float2(*(const __half2*)&vv.y); acc[2] = fmaf(w, p.x, acc[2]); acc[3] = fmaf(w, p.y, acc[3]);
        p = __half22float2(*(const __half2*)&vv.z); acc[4] = fmaf(w, p.x, acc[4]); acc[5] = fmaf(w, p.y, acc[5]);
        p = __half22float2(*(const __half2*)&vv.w); acc[6] = fmaf(w, p.x, acc[6]); acc[7] = fmaf(w, p.y, acc[7]);
    }
    float inv = 1.0f / fmaxf((float)(end - beg), 1.0f);
    // dst: aggX -> cols 0-127 (lanes 0-15), aggH -> cols 256-383 (lanes 16-31)
    uint32_t dst_off = ((uint32_t)(lane >> 4) << 8) + ((uint32_t)(lane & 15) << 3);
    __half2 h0 = __floats2half2_rn(acc[0] * inv, acc[1] * inv);
    __half2 h1 = __floats2half2_rn(acc[2] * inv, acc[3] * inv);
    __half2 h2 = __floats2half2_rn(acc[4] * inv, acc[5] * inv);
    __half2 h3 = __floats2half2_rn(acc[6] * inv, acc[7] * inv);
    uint4 out;
    out.x = *(uint32_t*)&h0; out.y = *(uint32_t*)&h1;
    out.z = *(uint32_t*)&h2; out.w = *(uint32_t*)&h3;
    *(uint4*)(g_Ah + (size_t)warp * KTOT + dst_off) = out;
}

// ===================== fp16 warp-MMA GEMM + fused LSTM (R13-proven) =====================
// Block 128x128, 256 threads (8 warps 2x4), warp tile 64x32, 2 CTAs/SM.
// K: 16 tiles of 32 fp16, double-buffered. SMEM rows: 32 fp16 (64B) + 16B pad = 80B.
#define ROW_B    80
#define TILE_B   (128 * ROW_B)        // 10240
#define STAGE_B  (2 * TILE_B)         // 20480 (A then B)
#define DSTRIDE  132
#define GEMM_SMEM (128 * DSTRIDE * 4) // 67584 (covers 2*STAGE_B = 40960 pipeline)

__global__ void __launch_bounds__(256, 2) gemm_lstm_kernel(
    const float* __restrict__ C,
    const float* __restrict__ bx, const float* __restrict__ bh, const float* __restrict__ bg,
    const float* __restrict__ wc,
    float* __restrict__ outH, float* __restrict__ outC)
{
    extern __shared__ char sm[];
    uint32_t smb = smem_to_u32(sm);

    int tid = threadIdx.x;
    int wid = tid >> 5, lid = tid & 31;
    int ntile = blockIdx.x;        // 0..3 (128 n-cols each)
    int row0  = blockIdx.y * 128;

    // cp.async mapping: thread -> row = tid>>1, half = tid&1 (16 fp16 = 32B)
    int lrow = tid >> 1;
    int half = tid & 1;
    int arow = row0 + lrow; if (arow >= N_NODES) arow = N_NODES - 1;
    int brow = ntile * 128 + lrow;
    uint32_t dst_off = (uint32_t)lrow * ROW_B + half * 32;
    const __half* Ap = g_Ah + (size_t)arow * KTOT + half * 16;
    const __half* Bp = g_Bh + (size_t)brow * KTOT + half * 16;

    // warp tiling: 2x4, warp tile 64x32
    int mw = (wid >> 2) * 64;
    int nw = (wid & 3) * 32;
    int a_r = ((lid >> 3) & 1) * 8 + (lid & 7);
    int a_k = (lid >> 4) * 8;
    int b_r = (lid >> 4) * 8 + (lid & 7);
    int b_k = ((lid >> 3) & 1) * 8;

    uint32_t offA = (uint32_t)(mw + a_r) * ROW_B + a_k * 2;
    uint32_t offB = (uint32_t)TILE_B + (uint32_t)(nw + b_r) * ROW_B + b_k * 2;

    float acc[4][4][4];
#pragma unroll
    for (int i = 0; i < 4; i++)
#pragma unroll
        for (int j = 0; j < 4; j++)
#pragma unroll
            for (int q = 0; q < 4; q++) acc[i][j][q] = 0.f;

    // prologue: k-tile 0 -> stage 0
    {
        uint32_t da = smb + dst_off;
        uint32_t db = smb + TILE_B + dst_off;
        CP_ASYNC16(da,      Ap);
        CP_ASYNC16(da + 16, Ap + 8);
        CP_ASYNC16(db,      Bp);
        CP_ASYNC16(db + 16, Bp + 8);
        CP_COMMIT();
    }

    int buf = 0;
    for (int kt = 0; kt < 16; kt++) {
        CP_WAIT(0);
        __syncthreads();
        if (kt < 15) {
            int k1 = (kt + 1) * 32;
            uint32_t sbb = smb + (buf ^ 1) * STAGE_B;
            uint32_t da = sbb + dst_off;
            uint32_t db = sbb + TILE_B + dst_off;
            CP_ASYNC16(da,      Ap + k1);
            CP_ASYNC16(da + 16, Ap + k1 + 8);
            CP_ASYNC16(db,      Bp + k1);
            CP_ASYNC16(db + 16, Bp + k1 + 8);
            CP_COMMIT();
        }

        uint32_t sstage = smb + buf * STAGE_B;
        uint32_t aA = sstage + offA;
        uint32_t aB = sstage + offB;

#pragma unroll
        for (int ks = 0; ks < 2; ks++) {
            uint32_t koff = ks * 32;   // 16 fp16 = 32B
            uint32_t Bf[4][2];
#pragma unroll
            for (int nj = 0; nj < 2; nj++) {
                LDSM_X4(Bf[2 * nj][0], Bf[2 * nj][1], Bf[2 * nj + 1][0], Bf[2 * nj + 1][1],
                        aB + nj * (16 * ROW_B) + koff);
            }
#pragma unroll
            for (int mi = 0; mi < 4; mi++) {
                uint32_t Af[4];
                LDSM_X4(Af[0], Af[1], Af[2], Af[3], aA + mi * (16 * ROW_B) + koff);
#pragma unroll
                for (int ni = 0; ni < 4; ni++)
                    MMA_F16(acc[mi][ni], Af, Bf[ni]);
            }
        }
        buf ^= 1;
    }
    __syncthreads();

    // epilogue: acc -> smem D[128][132]
    float* sD = (float*)sm;
    {
        int r0 = mw + (lid >> 2);
        int c0 = nw + (lid & 3) * 2;
#pragma unroll
        for (int mi = 0; mi < 4; mi++)
#pragma unroll
            for (int ni = 0; ni < 4; ni++) {
                int rr = r0 + mi * 16, cc = c0 + ni * 8;
                sD[rr * DSTRIDE + cc]           = acc[mi][ni][0];
                sD[rr * DSTRIDE + cc + 1]       = acc[mi][ni][1];
                sD[(rr + 8) * DSTRIDE + cc]     = acc[mi][ni][2];
                sD[(rr + 8) * DSTRIDE + cc + 1] = acc[mi][ni][3];
            }
    }
    __syncthreads();

    // fused LSTM: thread -> row = tid>>1, 16 outputs
    {
        int row = tid >> 1;
        int r = row0 + row;
        if (r < N_NODES) {
            int ob = (tid & 1) * 16;
            int o0 = ntile * 32 + ob;
#pragma unroll 4
            for (int j = 0; j < 16; j += 4) {
                float4 cold4 = *(const float4*)&C[(size_t)r * DIM + o0 + j];
                float co[4] = {cold4.x, cold4.y, cold4.z, cold4.w};
                float hnew[4], cnew[4];
#pragma unroll
                for (int q = 0; q < 4; q++) {
                    int o = o0 + j + q;
                    float4 gq = *(float4*)&sD[row * DSTRIDE + (ob + j + q) * 4];
                    float gI = gq.x + bx[0 * DIM + o] + bh[0 * DIM + o] + bg[0 * DIM + o] + wc[0 * DIM + o] * co[q];
                    float gF = gq.y + bx[1 * DIM + o] + bh[1 * DIM + o] + bg[1 * DIM + o] + wc[1 * DIM + o] * co[q];
                    float gT = gq.z + bx[2 * DIM + o] + bh[2 * DIM + o] + bg[2 * DIM + o];
                    float I = 1.f / (1.f + expf(-gI));
                    float F = 1.f / (1.f + expf(-gF));
                    float T = tanhf(gT);
                    float cn = fmaf(F, co[q], I * T);
                    float gO = gq.w + bx[3 * DIM + o] + bh[3 * DIM + o] + bg[3 * DIM + o] + wc[2 * DIM + o] * cn;
                    float O = 1.f / (1.f + expf(-gO));
                    hnew[q] = O * tanhf(cn);
                    cnew[q] = cn;
                }
                *(float4*)&outH[(size_t)r * DIM + o0 + j] = make_float4(hnew[0], hnew[1], hnew[2], hnew[3]);
                *(float4*)&outC[(size_t)r * DIM + o0 + j] = make_float4(cnew[0], cnew[1], cnew[2], cnew[3]);
            }
        }
    }
}

// ===================== launch =====================
extern "C" void kernel_launch(void* const* d_in, const int* in_sizes, int n_in,
                              void* d_out, int out_size) {
    const float* X    = (const float*)d_in[0];
    const int*   ei   = (const int*)  d_in[1];
    const float* ew   = (const float*)d_in[2];
    const float* H    = (const float*)d_in[3];
    const float* C    = (const float*)d_in[4];
    const float* Wx_l = (const float*)d_in[5];
    const float* Wx_r = (const float*)d_in[6];
    const float* bx   = (const float*)d_in[7];
    const float* Wh_l = (const float*)d_in[8];
    const float* Wh_r = (const float*)d_in[9];
    const float* bh   = (const float*)d_in[10];
    const float* wc   = (const float*)d_in[11];
    const float* bg   = (const float*)d_in[12];

    float* outH = (float*)d_out;
    float* outC = outH + (size_t)N_NODES * DIM;

    cudaFuncSetAttribute(gemm_lstm_kernel, cudaFuncAttributeMaxDynamicSharedMemorySize, GEMM_SMEM);

    count_prep_scan_kernel<<<CPS_BLOCKS, 256>>>(ei, X, H, Wx_l, Wx_r, Wh_l, Wh_r);
    scatter_kernel<<<(N_EDGES + 1023) / 1024, 256>>>(ei, ew);
    aggregate_kernel<<<(N_NODES * 32 + 255) / 256, 256>>>();

    dim3 grid(4, MTILES);
    gemm_lstm_kernel<<<grid, 256, GEMM_SMEM>>>(C, bx, bh, bg, wc, outH, outC);
}

// round 17
// speedup vs baseline: 1.0864x; 1.0346x over previous
#include <cuda_runtime.h>
#include <cuda_fp16.h>
#include <math.h>
#include <stdint.h>

#define N_NODES 20000
#define N_EDGES 640000
#define DIM     128
#define KTOT    512     // A cols: [aggX | X | aggH | H]
#define NCOL    512     // 4 gates * 128 outputs, col = o*4 + g
#define MTILES  157     // ceil(20000/128)

// ===================== helpers =====================
__device__ __forceinline__ uint32_t smem_to_u32(const void* p) {
    uint32_t a;
    asm("{ .reg .u64 t; cvta.to.shared.u64 t, %1; cvt.u32.u64 %0, t; }" : "=r"(a) : "l"(p));
    return a;
}
#define CP_ASYNC16(sm, gp) \
    asm volatile("cp.async.cg.shared.global [%0], [%1], 16;" :: "r"(sm), "l"(gp) : "memory")
#define CP_COMMIT() asm volatile("cp.async.commit_group;" ::: "memory")
#define CP_WAIT(n)  asm volatile("cp.async.wait_group %0;" :: "n"(n) : "memory")

#define LDSM_X4(r0, r1, r2, r3, a) \
    asm volatile("ldmatrix.sync.aligned.m8n8.x4.shared.b16 {%0,%1,%2,%3}, [%4];" \
        : "=r"(r0), "=r"(r1), "=r"(r2), "=r"(r3) : "r"(a))

#define MMA_F16(d, a, b) \
    asm volatile("mma.sync.aligned.m16n8k16.row.col.f32.f16.f16.f32 " \
        "{%0,%1,%2,%3}, {%4,%5,%6,%7}, {%8,%9}, {%0,%1,%2,%3};" \
        : "+f"((d)[0]), "+f"((d)[1]), "+f"((d)[2]), "+f"((d)[3]) \
        : "r"((a)[0]), "r"((a)[1]), "r"((a)[2]), "r"((a)[3]), "r"((b)[0]), "r"((b)[1]))

// ===================== scratch =====================
__device__ int   g_cnt[N_NODES + 1];                    // slot N_NODES = done-counter
__device__ int   g_off[N_NODES + 1];
__device__ int   g_rank[N_EDGES];                       // edge rank within its dst bucket
__device__ uint2 g_edge[N_EDGES];                       // {src, weight bits}
__device__ __half g_Ah[(size_t)N_NODES * KTOT];         // fp16 A matrix [node][512]
__device__ __half g_Bh[(size_t)NCOL * KTOT];            // fp16 B^T [n][k], n = o*4+g

#define COUNT_BLOCKS 625                                 // 4 edges/thread
#define CONV_N2 (N_NODES * 64)                           // 2 cols per thread
#define PACK_N  (NCOL * KTOT)
#define PREP_BLOCKS ((CONV_N2 + PACK_N + 255) / 256)
#define CPS_BLOCKS  (COUNT_BLOCKS + PREP_BLOCKS)

// ===================== fused count(+rank) + prep + (last block) scan =====================
__global__ void count_prep_scan_kernel(const int* __restrict__ ei,
                                       const float* __restrict__ X, const float* __restrict__ H,
                                       const float* __restrict__ Wx_l, const float* __restrict__ Wx_r,
                                       const float* __restrict__ Wh_l, const float* __restrict__ Wh_r) {
    int b = blockIdx.x;
    if (b < COUNT_BLOCKS) {
        int e0 = b * 1024 + threadIdx.x;
#pragma unroll
        for (int j = 0; j < 4; j++) {
            int e = e0 + j * 256;
            if (e < N_EDGES) {
                int d = ei[N_EDGES + e];
                g_rank[e] = atomicAdd(&g_cnt[d], 1);
            }
        }
    } else {
        int idx = (b - COUNT_BLOCKS) * 256 + threadIdx.x;
        if (idx < CONV_N2) {
            int r = idx >> 6, c2 = idx & 63;          // 2 cols per thread
            float2 xv = *(const float2*)(X + (size_t)r * DIM + c2 * 2);
            float2 hv = *(const float2*)(H + (size_t)r * DIM + c2 * 2);
            size_t ba = (size_t)r * KTOT;
            *(__half2*)(g_Ah + ba + 128 + c2 * 2) = __floats2half2_rn(xv.x, xv.y);
            *(__half2*)(g_Ah + ba + 384 + c2 * 2) = __floats2half2_rn(hv.x, hv.y);
        } else {
            int j = idx - CONV_N2;
            if (j < PACK_N) {
                int n = j >> 9;
                int k = j & 511;
                int o = n >> 2, g = n & 3;
                int kb = k >> 7, d = k & 127;
                const float* W = (kb == 0) ? Wx_l : (kb == 1) ? Wx_r : (kb == 2) ? Wh_l : Wh_r;
                g_Bh[j] = __float2half_rn(W[(g * DIM + d) * DIM + o]);
            }
        }
    }

    // ---- last-block scan ----
    __threadfence();
    __shared__ int s_last;
    if (threadIdx.x == 0)
        s_last = (atomicAdd(&g_cnt[N_NODES], 1) == CPS_BLOCKS - 1) ? 1 : 0;
    __syncthreads();
    if (!s_last) return;

    const int PER = 79;
    int t = threadIdx.x;
    int base = t * PER;
    int sum = 0;
    for (int j = 0; j < PER; j++) {
        int i = base + j;
        if (i < N_NODES) sum += g_cnt[i];
    }
    int lane = t & 31, warp = t >> 5;
    int x = sum;
#pragma unroll
    for (int o = 1; o < 32; o <<= 1) {
        int y = __shfl_up_sync(0xFFFFFFFFu, x, o);
        if (lane >= o) x += y;
    }
    __shared__ int wsum[8];
    if (lane == 31) wsum[warp] = x;
    __syncthreads();
    if (warp == 0 && lane < 8) {
        int w = wsum[lane];
#pragma unroll
        for (int o = 1; o < 8; o <<= 1) {
            int y = __shfl_up_sync(0xFFu, w, o);
            if (lane >= o) w += y;
        }
        wsum[lane] = w;
    }
    __syncthreads();
    int warpbase = (warp > 0) ? wsum[warp - 1] : 0;
    int excl = warpbase + x - sum;
    for (int j = 0; j < PER; j++) {
        int i = base + j;
        if (i < N_NODES) {
            g_off[i] = excl;
            excl += g_cnt[i];
        }
    }
    if (t == 255) g_off[N_NODES] = warpbase + x;
}

// ===================== scatter: atomic-free via precomputed ranks, 4 edges/thread =====================
__global__ void scatter_kernel(const int* __restrict__ ei, const float* __restrict__ ew) {
    int e0 = blockIdx.x * 1024 + threadIdx.x;
    int dd[4], ss[4], rr[4];
    float ww[4];
#pragma unroll
    for (int j = 0; j < 4; j++) {
        int e = e0 + j * 256;
        if (e < N_EDGES) {
            dd[j] = ei[N_EDGES + e];
            ss[j] = ei[e];
            ww[j] = ew[e];
            rr[j] = g_rank[e];
        } else dd[j] = -1;
    }
#pragma unroll
    for (int j = 0; j < 4; j++)
        if (dd[j] >= 0) {
            int p = g_off[dd[j]] + rr[j];
            g_edge[p] = make_uint2((uint32_t)ss[j], __float_as_uint(ww[j]));
        }
}

// ===================== aggregation: 1 warp/node, lane-split X/H, 2-edge unroll (R11-proven) =====================
__global__ void aggregate_kernel() {
    int warp = (blockIdx.x * blockDim.x + threadIdx.x) >> 5;
    int lane = threadIdx.x & 31;
    if (warp >= N_NODES) return;
    int beg = g_off[warp], end = g_off[warp + 1];
    // lanes 0-15 -> X chunk (src cols 128-255), lanes 16-31 -> H chunk (src cols 384-511)
    uint32_t src_off = 128u + ((uint32_t)(lane >> 4) << 8) + ((uint32_t)(lane & 15) << 3);
    float acc[8] = {0.f, 0.f, 0.f, 0.f, 0.f, 0.f, 0.f, 0.f};
    int e = beg;
    for (; e + 1 < end; e += 2) {
        uint2 ed0 = __ldg(&g_edge[e]);
        uint2 ed1 = __ldg(&g_edge[e + 1]);
        float w0 = __uint_as_float(ed0.y), w1 = __uint_as_float(ed1.y);
        uint4 v0 = __ldg((const uint4*)(g_Ah + (size_t)ed0.x * KTOT + src_off));
        uint4 v1 = __ldg((const uint4*)(g_Ah + (size_t)ed1.x * KTOT + src_off));
        float2 p;
        p = __half22float2(*(const __half2*)&v0.x); acc[0] = fmaf(w0, p.x, acc[0]); acc[1] = fmaf(w0, p.y, acc[1]);
        p = __half22float2(*(const __half2*)&v0.y); acc[2] = fmaf(w0, p.x, acc[2]); acc[3] = fmaf(w0, p.y, acc[3]);
        p = __half22float2(*(const __half2*)&v0.z); acc[4] = fmaf(w0, p.x, acc[4]); acc[5] = fmaf(w0, p.y, acc[5]);
        p = __half22float2(*(const __half2*)&v0.w); acc[6] = fmaf(w0, p.x, acc[6]); acc[7] = fmaf(w0, p.y, acc[7]);
        p = __half22float2(*(const __half2*)&v1.x); acc[0] = fmaf(w1, p.x, acc[0]); acc[1] = fmaf(w1, p.y, acc[1]);
        p = __half22float2(*(const __half2*)&v1.y); acc[2] = fmaf(w1, p.x, acc[2]); acc[3] = fmaf(w1, p.y, acc[3]);
        p = __half22float2(*(const __half2*)&v1.z); acc[4] = fmaf(w1, p.x, acc[4]); acc[5] = fmaf(w1, p.y, acc[5]);
        p = __half22float2(*(const __half2*)&v1.w); acc[6] = fmaf(w1, p.x, acc[6]); acc[7] = fmaf(w1, p.y, acc[7]);
    }
    if (e < end) {
        uint2 ed = __ldg(&g_edge[e]);
        float w = __uint_as_float(ed.y);
        uint4 v = __ldg((const uint4*)(g_Ah + (size_t)ed.x * KTOT + src_off));
        float2 p;
        p = __half22float2(*(const __half2*)&v.x); acc[0] = fmaf(w, p.x, acc[0]); acc[1] = fmaf(w, p.y, acc[1]);
        p = __half22float2(*(const __half2*)&v.y); acc[2] = fmaf(w, p.x, acc[2]); acc[3] = fmaf(w, p.y, acc[3]);
        p = __half22float2(*(const __half2*)&v.z); acc[4] = fmaf(w, p.x, acc[4]); acc[5] = fmaf(w, p.y, acc[5]);
        p = __half22float2(*(const __half2*)&v.w); acc[6] = fmaf(w, p.x, acc[6]); acc[7] = fmaf(w, p.y, acc[7]);
    }
    float inv = 1.0f / fmaxf((float)(end - beg), 1.0f);
    // dst: aggX -> cols 0-127 (lanes 0-15), aggH -> cols 256-383 (lanes 16-31)
    uint32_t dst_off = ((uint32_t)(lane >> 4) << 8) + ((uint32_t)(lane & 15) << 3);
    __half2 h0 = __floats2half2_rn(acc[0] * inv, acc[1] * inv);
    __half2 h1 = __floats2half2_rn(acc[2] * inv, acc[3] * inv);
    __half2 h2 = __floats2half2_rn(acc[4] * inv, acc[5] * inv);
    __half2 h3 = __floats2half2_rn(acc[6] * inv, acc[7] * inv);
    uint4 out;
    out.x = *(uint32_t*)&h0; out.y = *(uint32_t*)&h1;
    out.z = *(uint32_t*)&h2; out.w = *(uint32_t*)&h3;
    *(uint4*)(g_Ah + (size_t)warp * KTOT + dst_off) = out;
}

// ===================== fp16 warp-MMA GEMM + fused LSTM (R13-proven) =====================
// Block 128x128, 256 threads (8 warps 2x4), warp tile 64x32, 2 CTAs/SM.
// K: 16 tiles of 32 fp16, double-buffered. SMEM rows: 32 fp16 (64B) + 16B pad = 80B.
#define ROW_B    80
#define TILE_B   (128 * ROW_B)        // 10240
#define STAGE_B  (2 * TILE_B)         // 20480 (A then B)
#define DSTRIDE  132
#define GEMM_SMEM (128 * DSTRIDE * 4) // 67584 (covers 2*STAGE_B = 40960 pipeline)

__global__ void __launch_bounds__(256, 2) gemm_lstm_kernel(
    const float* __restrict__ C,
    const float* __restrict__ bx, const float* __restrict__ bh, const float* __restrict__ bg,
    const float* __restrict__ wc,
    float* __restrict__ outH, float* __restrict__ outC)
{
    extern __shared__ char sm[];
    uint32_t smb = smem_to_u32(sm);

    int tid = threadIdx.x;
    int wid = tid >> 5, lid = tid & 31;
    int ntile = blockIdx.x;        // 0..3 (128 n-cols each)
    int row0  = blockIdx.y * 128;

    // cp.async mapping: thread -> row = tid>>1, half = tid&1 (16 fp16 = 32B)
    int lrow = tid >> 1;
    int half = tid & 1;
    int arow = row0 + lrow; if (arow >= N_NODES) arow = N_NODES - 1;
    int brow = ntile * 128 + lrow;
    uint32_t dst_off = (uint32_t)lrow * ROW_B + half * 32;
    const __half* Ap = g_Ah + (size_t)arow * KTOT + half * 16;
    const __half* Bp = g_Bh + (size_t)brow * KTOT + half * 16;

    // warp tiling: 2x4, warp tile 64x32
    int mw = (wid >> 2) * 64;
    int nw = (wid & 3) * 32;
    int a_r = ((lid >> 3) & 1) * 8 + (lid & 7);
    int a_k = (lid >> 4) * 8;
    int b_r = (lid >> 4) * 8 + (lid & 7);
    int b_k = ((lid >> 3) & 1) * 8;

    uint32_t offA = (uint32_t)(mw + a_r) * ROW_B + a_k * 2;
    uint32_t offB = (uint32_t)TILE_B + (uint32_t)(nw + b_r) * ROW_B + b_k * 2;

    float acc[4][4][4];
#pragma unroll
    for (int i = 0; i < 4; i++)
#pragma unroll
        for (int j = 0; j < 4; j++)
#pragma unroll
            for (int q = 0; q < 4; q++) acc[i][j][q] = 0.f;

    // prologue: k-tile 0 -> stage 0
    {
        uint32_t da = smb + dst_off;
        uint32_t db = smb + TILE_B + dst_off;
        CP_ASYNC16(da,      Ap);
        CP_ASYNC16(da + 16, Ap + 8);
        CP_ASYNC16(db,      Bp);
        CP_ASYNC16(db + 16, Bp + 8);
        CP_COMMIT();
    }

    int buf = 0;
    for (int kt = 0; kt < 16; kt++) {
        CP_WAIT(0);
        __syncthreads();
        if (kt < 15) {
            int k1 = (kt + 1) * 32;
            uint32_t sbb = smb + (buf ^ 1) * STAGE_B;
            uint32_t da = sbb + dst_off;
            uint32_t db = sbb + TILE_B + dst_off;
            CP_ASYNC16(da,      Ap + k1);
            CP_ASYNC16(da + 16, Ap + k1 + 8);
            CP_ASYNC16(db,      Bp + k1);
            CP_ASYNC16(db + 16, Bp + k1 + 8);
            CP_COMMIT();
        }

        uint32_t sstage = smb + buf * STAGE_B;
        uint32_t aA = sstage + offA;
        uint32_t aB = sstage + offB;

#pragma unroll
        for (int ks = 0; ks < 2; ks++) {
            uint32_t koff = ks * 32;   // 16 fp16 = 32B
            uint32_t Bf[4][2];
#pragma unroll
            for (int nj = 0; nj < 2; nj++) {
                LDSM_X4(Bf[2 * nj][0], Bf[2 * nj][1], Bf[2 * nj + 1][0], Bf[2 * nj + 1][1],
                        aB + nj * (16 * ROW_B) + koff);
            }
#pragma unroll
            for (int mi = 0; mi < 4; mi++) {
                uint32_t Af[4];
                LDSM_X4(Af[0], Af[1], Af[2], Af[3], aA + mi * (16 * ROW_B) + koff);
#pragma unroll
                for (int ni = 0; ni < 4; ni++)
                    MMA_F16(acc[mi][ni], Af, Bf[ni]);
            }
        }
        buf ^= 1;
    }
    __syncthreads();

    // epilogue: acc -> smem D[128][132]
    float* sD = (float*)sm;
    {
        int r0 = mw + (lid >> 2);
        int c0 = nw + (lid & 3) * 2;
#pragma unroll
        for (int mi = 0; mi < 4; mi++)
#pragma unroll
            for (int ni = 0; ni < 4; ni++) {
                int rr = r0 + mi * 16, cc = c0 + ni * 8;
                sD[rr * DSTRIDE + cc]           = acc[mi][ni][0];
                sD[rr * DSTRIDE + cc + 1]       = acc[mi][ni][1];
                sD[(rr + 8) * DSTRIDE + cc]     = acc[mi][ni][2];
                sD[(rr + 8) * DSTRIDE + cc + 1] = acc[mi][ni][3];
            }
    }
    __syncthreads();

    // fused LSTM: thread -> row = tid>>1, 16 outputs
    {
        int row = tid >> 1;
        int r = row0 + row;
        if (r < N_NODES) {
            int ob = (tid & 1) * 16;
            int o0 = ntile * 32 + ob;
#pragma unroll 4
            for (int j = 0; j < 16; j += 4) {
                float4 cold4 = *(const float4*)&C[(size_t)r * DIM + o0 + j];
                float co[4] = {cold4.x, cold4.y, cold4.z, cold4.w};
                float hnew[4], cnew[4];
#pragma unroll
                for (int q = 0; q < 4; q++) {
                    int o = o0 + j + q;
                    float4 gq = *(float4*)&sD[row * DSTRIDE + (ob + j + q) * 4];
                    float gI = gq.x + bx[0 * DIM + o] + bh[0 * DIM + o] + bg[0 * DIM + o] + wc[0 * DIM + o] * co[q];
                    float gF = gq.y + bx[1 * DIM + o] + bh[1 * DIM + o] + bg[1 * DIM + o] + wc[1 * DIM + o] * co[q];
                    float gT = gq.z + bx[2 * DIM + o] + bh[2 * DIM + o] + bg[2 * DIM + o];
                    float I = 1.f / (1.f + expf(-gI));
                    float F = 1.f / (1.f + expf(-gF));
                    float T = tanhf(gT);
                    float cn = fmaf(F, co[q], I * T);
                    float gO = gq.w + bx[3 * DIM + o] + bh[3 * DIM + o] + bg[3 * DIM + o] + wc[2 * DIM + o] * cn;
                    float O = 1.f / (1.f + expf(-gO));
                    hnew[q] = O * tanhf(cn);
                    cnew[q] = cn;
                }
                *(float4*)&outH[(size_t)r * DIM + o0 + j] = make_float4(hnew[0], hnew[1], hnew[2], hnew[3]);
                *(float4*)&outC[(size_t)r * DIM + o0 + j] = make_float4(cnew[0], cnew[1], cnew[2], cnew[3]);
            }
        }
    }
}

// ===================== launch =====================
extern "C" void kernel_launch(void* const* d_in, const int* in_sizes, int n_in,
                              void* d_out, int out_size) {
    const float* X    = (const float*)d_in[0];
    const int*   ei   = (const int*)  d_in[1];
    const float* ew   = (const float*)d_in[2];
    const float* H    = (const float*)d_in[3];
    const float* C    = (const float*)d_in[4];
    const float* Wx_l = (const float*)d_in[5];
    const float* Wx_r = (const float*)d_in[6];
    const float* bx   = (const float*)d_in[7];
    const float* Wh_l = (const float*)d_in[8];
    const float* Wh_r = (const float*)d_in[9];
    const float* bh   = (const float*)d_in[10];
    const float* wc   = (const float*)d_in[11];
    const float* bg   = (const float*)d_in[12];

    float* outH = (float*)d_out;
    float* outC = outH + (size_t)N_NODES * DIM;

    cudaFuncSetAttribute(gemm_lstm_kernel, cudaFuncAttributeMaxDynamicSharedMemorySize, GEMM_SMEM);

    void* cnt_ptr = nullptr;
    cudaGetSymbolAddress(&cnt_ptr, g_cnt);
    cudaMemsetAsync(cnt_ptr, 0, sizeof(int) * (N_NODES + 1));

    count_prep_scan_kernel<<<CPS_BLOCKS, 256>>>(ei, X, H, Wx_l, Wx_r, Wh_l, Wh_r);
    scatter_kernel<<<(N_EDGES + 1023) / 1024, 256>>>(ei, ew);
    aggregate_kernel<<<(N_NODES * 32 + 255) / 256, 256>>>();

    dim3 grid(4, MTILES);
    gemm_lstm_kernel<<<grid, 256, GEMM_SMEM>>>(C, bx, bh, bg, wc, outH, outC);
}